// round 14
// baseline (speedup 1.0000x reference)
#include <cuda_runtime.h>
#include <cuda_fp16.h>
#include <cstdint>

// ===================== problem constants =====================
#define N_ROWS 16384
#define DIMK   256
#define TILE   128
#define NCTA   148
#define NTHR   512

// exp((s-1)/T) = 2^(s*C1 - C1),  C1 = log2(e)/T,  T = 0.07
#define C1F   20.60992915555662f
#define INV_T 14.285714285714286f

// ===================== device globals (no allocs allowed) =====================
__device__ uint4 g_emb4[N_ROWS * DIMK / 8];   // normalized fp16 rows, 8 halves per uint4
__device__ float g_sum[N_ROWS];               // Σ_j exp((s_rj-1)/T) per row (atomic)
__device__ float g_diag[N_ROWS];
__device__ unsigned int g_done = 0;

// ===================== helpers =====================
__device__ __forceinline__ uint32_t smem_to_u32(const void* smem_ptr) {
    uint32_t addr;
    asm("{ .reg .u64 tmp; cvta.to.shared.u64 tmp, %1; cvt.u32.u64 %0, tmp; }"
        : "=r"(addr) : "l"(smem_ptr));
    return addr;
}

__device__ __forceinline__ void ldsm4(uint32_t* r, uint32_t addr) {
    asm volatile("ldmatrix.sync.aligned.m8n8.x4.shared.b16 {%0,%1,%2,%3}, [%4];"
        : "=r"(r[0]), "=r"(r[1]), "=r"(r[2]), "=r"(r[3]) : "r"(addr));
}

// f16 inputs, f16 accumulators: C/D are 2 regs (4 packed halves).
__device__ __forceinline__ void mma16816h(uint32_t* c, const uint32_t* a, uint32_t b0, uint32_t b1) {
    asm volatile(
        "mma.sync.aligned.m16n8k16.row.col.f16.f16.f16.f16 "
        "{%0,%1}, {%2,%3,%4,%5}, {%6,%7}, {%0,%1};"
        : "+r"(c[0]), "+r"(c[1])
        : "r"(a[0]), "r"(a[1]), "r"(a[2]), "r"(a[3]), "r"(b0), "r"(b1));
}

__device__ __forceinline__ void mma16816h_z(uint32_t* c, const uint32_t* a, uint32_t b0, uint32_t b1) {
    asm volatile(
        "mma.sync.aligned.m16n8k16.row.col.f16.f16.f16.f16 "
        "{%0,%1}, {%2,%3,%4,%5}, {%6,%7}, {%8,%8};"
        : "=r"(c[0]), "=r"(c[1])
        : "r"(a[0]), "r"(a[1]), "r"(a[2]), "r"(a[3]), "r"(b0), "r"(b1), "r"(0u));
}

__device__ __forceinline__ float ex2f(float x) {
    float r;
    asm("ex2.approx.f32 %0, %1;" : "=f"(r) : "f"(x));
    return r;
}

__device__ __forceinline__ void red_add(float* p, float v) {
    asm volatile("red.global.add.f32 [%0], %1;" :: "l"(p), "f"(v) : "memory");
}

#define CP_ASYNC16(dst_u32, src_ptr) \
    asm volatile("cp.async.cg.shared.global [%0], [%1], 16;" \
        :: "r"(dst_u32), "l"(src_ptr) : "memory")
#define CP_COMMIT() asm volatile("cp.async.commit_group;" ::: "memory")
#define CP_WAIT0()  asm volatile("cp.async.wait_group 0;" ::: "memory")

// Half-CTA named barrier: halves 0/1 use HW barriers 1/2 with 256 threads each.
#define BAR_HALF(h) \
    asm volatile("bar.sync %0, 256;" :: "r"(1 + (h)) : "memory")

// ===================== kernel 1: L2-normalize rows -> fp16 + zero accumulators =====================
__global__ __launch_bounds__(256) void norm_kernel(const float* __restrict__ in) {
    size_t gid = (size_t)blockIdx.x * 256 + threadIdx.x;
    if (gid < N_ROWS) g_sum[gid] = 0.0f;
    if (gid == 0) g_done = 0;

    int wid = threadIdx.x >> 5;
    int lane = threadIdx.x & 31;
    int row = blockIdx.x * 8 + wid;

    const float4* p = reinterpret_cast<const float4*>(in + (size_t)row * DIMK) + lane * 2;
    float4 a = p[0];
    float4 b = p[1];
    float ss = a.x * a.x + a.y * a.y + a.z * a.z + a.w * a.w
             + b.x * b.x + b.y * b.y + b.z * b.z + b.w * b.w;
#pragma unroll
    for (int o = 16; o > 0; o >>= 1) ss += __shfl_xor_sync(0xffffffffu, ss, o);

    float nrm = fmaxf(sqrtf(ss), 1e-12f);
    float sc = 1.0f / nrm;

    __half2 h0 = __floats2half2_rn(a.x * sc, a.y * sc);
    __half2 h1 = __floats2half2_rn(a.z * sc, a.w * sc);
    __half2 h2 = __floats2half2_rn(b.x * sc, b.y * sc);
    __half2 h3 = __floats2half2_rn(b.z * sc, b.w * sc);
    uint4 u;
    u.x = *reinterpret_cast<uint32_t*>(&h0);
    u.y = *reinterpret_cast<uint32_t*>(&h1);
    u.z = *reinterpret_cast<uint32_t*>(&h2);
    u.w = *reinterpret_cast<uint32_t*>(&h3);
    g_emb4[(size_t)row * 32 + lane] = u;
}

// ===================== kernel 2: triangular GEMM + symmetric LSE + final reduce =====================
// SMEM: A @0 (64KB, shared by both halves),
//       4 B slabs of 32KB: half h pair-slabs {SLAB(h,0), SLAB(h,1)},
//       s_red[16] tail
#define SM_A     0
#define SM_B     65536
#define SLAB(h, b) (SM_B + (((h) * 2 + (b)) << 15))
#define SM_TAIL  196608
#define DYN_SMEM (196608 + 128)

// A tile: 128 rows x 512B, per-row 16B-chunk XOR swizzle. All 512 threads.
__device__ __forceinline__ void load_A_async(uint32_t dst_u, int row0, int tid) {
#pragma unroll
    for (int it = 0; it < 8; ++it) {
        int c = tid + it * NTHR;          // 0..4095
        int i = c >> 5;                   // row 0..127
        int j = c & 31;
        uint32_t off = ((uint32_t)i << 9) + ((uint32_t)(j ^ (i & 7)) << 4);
        CP_ASYNC16(dst_u + off, &g_emb4[(size_t)(row0 + i) * 32 + j]);
    }
}

// B half-tile: 64 rows (J*128 + h*64 ...) x 512B, loaded by the half's 256 threads.
__device__ __forceinline__ void load_B_async(uint32_t dst_u, int J, int h, int lt) {
#pragma unroll
    for (int it = 0; it < 8; ++it) {
        int c = lt + it * 256;            // 0..2047
        int i = c >> 5;                   // row 0..63
        int j = c & 31;
        uint32_t off = ((uint32_t)i << 9) + ((uint32_t)(j ^ (i & 7)) << 4);
        CP_ASYNC16(dst_u + off, &g_emb4[(size_t)(J * TILE + h * 64 + i) * 32 + j]);
    }
}

// Column flush: shfl-reduce over the 8 g-lanes, lanes 0-3 RED their 8 cols.
__device__ __forceinline__ void col_flush(
    float (&colacc)[8], bool skip, int base_col, int warp_n, int lane)
{
#pragma unroll
    for (int j = 0; j < 8; j++) {
        float v = colacc[j];
        v += __shfl_xor_sync(0xffffffffu, v, 4);
        v += __shfl_xor_sync(0xffffffffu, v, 8);
        v += __shfl_xor_sync(0xffffffffu, v, 16);
        if (lane < 4 && !skip) {
            int cc = warp_n * 32 + (j >> 1) * 8 + lane * 2 + (j & 1);
            red_add(&g_sum[base_col + cc], v);
        }
        colacc[j] = 0.0f;
    }
}

// Epilogue + column flush for one 128x32 warp-slice of tile J (f16 packed acc).
__device__ __forceinline__ void epi_tile(
    const uint32_t (&acc)[2][4][2], float (&rowacc)[4], float (&colacc)[8],
    int I, int J, int h, int warp_m, int warp_n, int g, int tg, int lane)
{
    bool diag_tile = (J == I);
#pragma unroll
    for (int mf = 0; mf < 2; mf++)
#pragma unroll
        for (int nf = 0; nf < 4; nf++) {
            __half2 h01 = *reinterpret_cast<const __half2*>(&acc[mf][nf][0]);
            __half2 h23 = *reinterpret_cast<const __half2*>(&acc[mf][nf][1]);
            float2 f01 = __half22float2(h01);   // e0,e1 : row g,   cols 2tg,2tg+1
            float2 f23 = __half22float2(h23);   // e2,e3 : row g+8
            float sv[4] = { f01.x, f01.y, f23.x, f23.y };
#pragma unroll
            for (int e = 0; e < 4; e++) {
                float s = sv[e];
                float ex = ex2f(fmaf(s, C1F, -C1F));   // exp((s-1)/T)
                rowacc[mf * 2 + (e >> 1)] += ex;
                colacc[nf * 2 + (e & 1)] += ex;
                if (diag_tile) {
                    int rr = warp_m * 32 + mf * 16 + g + ((e >> 1) << 3);
                    int cloc = h * 64 + warp_n * 32 + nf * 8 + (tg << 1) + (e & 1);
                    if (rr == cloc) g_diag[I * TILE + rr] = s;
                }
            }
        }
    col_flush(colacc, diag_tile, J * TILE + h * 64, warp_n, lane);
}

// MMA over one pair (or single) of J tiles with A-fragment reuse per K-step.
template <bool DUAL>
__device__ __forceinline__ void mma_pair(
    uint32_t b_u0, uint32_t b_u1,
    uint32_t (&acc0)[2][4][2], uint32_t (&acc1)[2][4][2],
    const uint32_t (&a_base)[2], const uint32_t (&a_rx)[2], uint32_t a_hi,
    const uint32_t (&b_roff)[2], uint32_t b_rx, uint32_t b_kb)
{
#pragma unroll
    for (int ks = 0; ks < 16; ks++) {
        uint32_t a[2][4];
#pragma unroll
        for (int mf = 0; mf < 2; mf++) {
            uint32_t ch = ((uint32_t)(ks * 2) + a_hi) ^ a_rx[mf];
            ldsm4(a[mf], a_base[mf] + (ch << 4));
        }
        uint32_t chb = (((uint32_t)(ks * 2) + b_kb) ^ b_rx) << 4;

        uint32_t b0[2][4];
#pragma unroll
        for (int np = 0; np < 2; np++)
            ldsm4(b0[np], b_u0 + b_roff[np] + chb);
#pragma unroll
        for (int mf = 0; mf < 2; mf++)
#pragma unroll
            for (int np = 0; np < 2; np++) {
                if (ks == 0) {
                    mma16816h_z(acc0[mf][np * 2 + 0], a[mf], b0[np][0], b0[np][1]);
                    mma16816h_z(acc0[mf][np * 2 + 1], a[mf], b0[np][2], b0[np][3]);
                } else {
                    mma16816h(acc0[mf][np * 2 + 0], a[mf], b0[np][0], b0[np][1]);
                    mma16816h(acc0[mf][np * 2 + 1], a[mf], b0[np][2], b0[np][3]);
                }
            }
        if (DUAL) {
            uint32_t b1[2][4];
#pragma unroll
            for (int np = 0; np < 2; np++)
                ldsm4(b1[np], b_u1 + b_roff[np] + chb);
#pragma unroll
            for (int mf = 0; mf < 2; mf++)
#pragma unroll
                for (int np = 0; np < 2; np++) {
                    if (ks == 0) {
                        mma16816h_z(acc1[mf][np * 2 + 0], a[mf], b1[np][0], b1[np][1]);
                        mma16816h_z(acc1[mf][np * 2 + 1], a[mf], b1[np][2], b1[np][3]);
                    } else {
                        mma16816h(acc1[mf][np * 2 + 0], a[mf], b1[np][0], b1[np][1]);
                        mma16816h(acc1[mf][np * 2 + 1], a[mf], b1[np][2], b1[np][3]);
                    }
                }
        }
    }
}

__global__ __launch_bounds__(NTHR, 1) void gemm_lse_kernel(float* __restrict__ out) {
    extern __shared__ char smem[];
    uint32_t su = smem_to_u32(smem);
    float* s_red = reinterpret_cast<float*>(smem + SM_TAIL);
    __shared__ unsigned int s_ticket;

    int tid = threadIdx.x;
    int lane = tid & 31;
    int wid = tid >> 5;
    int h = wid >> 3;          // half 0/1
    int whh = wid & 7;         // warp in half
    int warp_m = whh >> 1;     // 0..3  (32 rows each)
    int warp_n = whh & 1;      // 0..1  (32 cols within the half's 64-col slice)
    int lt = tid & 255;        // thread in half
    const int g = lane >> 2;
    const int tg = lane & 3;
    const int cta = (int)blockIdx.x;

    // ldmatrix addressing (A buffer fixed at SM_A)
    uint32_t a_base[2];
    uint32_t a_rx[2];
#pragma unroll
    for (int mf = 0; mf < 2; mf++) {
        int r = warp_m * 32 + mf * 16 + (lane & 15);
        a_base[mf] = su + SM_A + ((uint32_t)r << 9);
        a_rx[mf] = (uint32_t)(r & 7);
    }
    uint32_t a_hi = (uint32_t)(lane >> 4);

    int nB = (lane & 7) + ((lane >> 4) << 3);
    uint32_t b_roff[2];
#pragma unroll
    for (int np = 0; np < 2; np++)
        b_roff[np] = (uint32_t)((warp_n * 32 + np * 16 + nB) << 9);   // row 0..63 in slab
    uint32_t b_rx = (uint32_t)(lane & 7);
    uint32_t b_kb = (uint32_t)((lane >> 3) & 1);

    float colacc[8];
#pragma unroll
    for (int j = 0; j < 8; j++) colacc[j] = 0.0f;

    // Balanced triangular chunking: 8256 tiles of 128x128 in pair order;
    // CTA gets 55/56 contiguous tiles.
    int t_beg = cta * 55 + (cta < 116 ? cta : 116);
    int t_end = t_beg + 55 + (cta < 116 ? 1 : 0);

    int t = t_beg;
    while (t < t_end) {
        int q = t / 129;
        int r = t - q * 129;
        int I, J0, rowrem;
        if (r < 128 - q) { I = q; J0 = q + r; rowrem = 128 - q - r; }
        else { int r2 = r - (128 - q); I = 127 - q; J0 = 127 - q + r2; rowrem = q + 1 - r2; }
        int cnt = min(t_end - t, rowrem);

        // ---------------- sweep: A = block I (shared); each half does the
        //                  h*64 column slice of B blocks J0..J0+cnt-1, in pairs ----
        float rowacc[4];
#pragma unroll
        for (int j = 0; j < 4; j++) rowacc[j] = 0.0f;

        load_A_async(su + SM_A, I * TILE, tid);
        load_B_async(su + SLAB(h, 0), J0, h, lt);
        if (cnt > 1)
            load_B_async(su + SLAB(h, 1), J0 + 1, h, lt);
        CP_COMMIT();
        CP_WAIT0();
        __syncthreads();   // publish A + both halves' first pair

        uint32_t b_u0 = su + SLAB(h, 0);
        uint32_t b_u1 = su + SLAB(h, 1);

        int i = 0;
        while (i < cnt) {
            bool dual = (i + 1 < cnt);
            uint32_t acc0[2][4][2], acc1[2][4][2];

            if (dual)
                mma_pair<true>(b_u0, b_u1, acc0, acc1,
                               a_base, a_rx, a_hi, b_roff, b_rx, b_kb);
            else
                mma_pair<false>(b_u0, b_u1, acc0, acc1,
                                a_base, a_rx, a_hi, b_roff, b_rx, b_kb);

            BAR_HALF(h);   // this half done reading its pair slabs

            // issue next pair's loads into the freed slabs (overlap with epi)
            int nxt = i + 2;
            int nload = cnt - nxt;
            if (nload > 0) {
                load_B_async(su + SLAB(h, 0), J0 + nxt, h, lt);
                if (nload > 1)
                    load_B_async(su + SLAB(h, 1), J0 + nxt + 1, h, lt);
                CP_COMMIT();
            }

            // epilogues (register-only + RED) overlap the cp.async
            epi_tile(acc0, rowacc, colacc, I, J0 + i, h, warp_m, warp_n, g, tg, lane);
            if (dual)
                epi_tile(acc1, rowacc, colacc, I, J0 + i + 1, h, warp_m, warp_n, g, tg, lane);

            if (nload > 0) {
                CP_WAIT0();
                BAR_HALF(h);   // publish new pair to the half
            }
            i += 2;
        }

        // Row flush: both halves RED their 64-col partials (atomics merge)
#pragma unroll
        for (int j = 0; j < 4; j++) {
            float v = rowacc[j];
            v += __shfl_xor_sync(0xffffffffu, v, 1);
            v += __shfl_xor_sync(0xffffffffu, v, 2);
            if (tg == 0) {
                int rr = warp_m * 32 + (j >> 1) * 16 + g + ((j & 1) << 3);
                red_add(&g_sum[I * TILE + rr], v);
            }
        }
        __syncthreads();   // both halves done with A before next sweep reloads it

        t += cnt;
    }

    // ---------------- last-CTA final reduction ----------------
    __threadfence();
    __syncthreads();
    if (tid == 0) s_ticket = atomicAdd(&g_done, 1u);
    __syncthreads();
    if (s_ticket == (unsigned)(gridDim.x - 1)) {
        __threadfence();
        float part = 0.0f;
#pragma unroll 4
        for (int rr = tid; rr < N_ROWS; rr += NTHR) {
            float S = g_sum[rr];
            part += (1.0f - g_diag[rr]) * INV_T + __logf(S);
        }
#pragma unroll
        for (int o = 16; o > 0; o >>= 1) part += __shfl_xor_sync(0xffffffffu, part, o);
        if (lane == 0) s_red[wid] = part;
        __syncthreads();
        if (tid == 0) {
            float v = 0.0f;
#pragma unroll
            for (int w = 0; w < 16; w++) v += s_red[w];
            out[0] = v * (1.0f / (float)N_ROWS);
            g_done = 0;   // reset for next graph replay
        }
    }
}

// ===================== launch =====================
extern "C" void kernel_launch(void* const* d_in, const int* in_sizes, int n_in,
                              void* d_out, int out_size) {
    (void)in_sizes; (void)n_in; (void)out_size;
    const float* emb = (const float*)d_in[0];

    cudaFuncSetAttribute(gemm_lse_kernel,
                         cudaFuncAttributeMaxDynamicSharedMemorySize, DYN_SMEM);

    norm_kernel<<<N_ROWS / 8, 256>>>(emb);
    gemm_lse_kernel<<<NCTA, NTHR, DYN_SMEM>>>((float*)d_out);
}

// round 16
// speedup vs baseline: 1.0989x; 1.0989x over previous
#include <cuda_runtime.h>
#include <cuda_bf16.h>
#include <cstdint>

// ===================== problem constants =====================
#define N_ROWS 16384
#define DIMK   256
#define TILE   128
#define NCTA   148
#define NTHR   512

// exp((s-1)/T) = 2^(s*C1 - C1),  C1 = log2(e)/T,  T = 0.07
#define C1F   20.60992915555662f
#define INV_T 14.285714285714286f

// ===================== device globals (no allocs allowed) =====================
__device__ uint4 g_emb4[N_ROWS * DIMK / 8];   // normalized bf16 rows
__device__ float g_sum[N_ROWS];               // Σ_j exp((s_rj-1)/T) per row (atomic)
__device__ float g_diag[N_ROWS];
__device__ unsigned int g_done = 0;

// ===================== helpers =====================
__device__ __forceinline__ uint32_t smem_to_u32(const void* smem_ptr) {
    uint32_t addr;
    asm("{ .reg .u64 tmp; cvta.to.shared.u64 tmp, %1; cvt.u32.u64 %0, tmp; }"
        : "=r"(addr) : "l"(smem_ptr));
    return addr;
}

__device__ __forceinline__ void ldsm4(uint32_t* r, uint32_t addr) {
    asm volatile("ldmatrix.sync.aligned.m8n8.x4.shared.b16 {%0,%1,%2,%3}, [%4];"
        : "=r"(r[0]), "=r"(r[1]), "=r"(r[2]), "=r"(r[3]) : "r"(addr));
}

__device__ __forceinline__ void mma16816(float* c, const uint32_t* a, uint32_t b0, uint32_t b1) {
    asm volatile(
        "mma.sync.aligned.m16n8k16.row.col.f32.bf16.bf16.f32 "
        "{%0,%1,%2,%3}, {%4,%5,%6,%7}, {%8,%9}, {%0,%1,%2,%3};"
        : "+f"(c[0]), "+f"(c[1]), "+f"(c[2]), "+f"(c[3])
        : "r"(a[0]), "r"(a[1]), "r"(a[2]), "r"(a[3]), "r"(b0), "r"(b1));
}

__device__ __forceinline__ void mma16816_z(float* c, const uint32_t* a, uint32_t b0, uint32_t b1) {
    asm volatile(
        "mma.sync.aligned.m16n8k16.row.col.f32.bf16.bf16.f32 "
        "{%0,%1,%2,%3}, {%4,%5,%6,%7}, {%8,%9}, {%10,%10,%10,%10};"
        : "=f"(c[0]), "=f"(c[1]), "=f"(c[2]), "=f"(c[3])
        : "r"(a[0]), "r"(a[1]), "r"(a[2]), "r"(a[3]), "r"(b0), "r"(b1), "f"(0.0f));
}

__device__ __forceinline__ float ex2f(float x) {
    float r;
    asm("ex2.approx.f32 %0, %1;" : "=f"(r) : "f"(x));
    return r;
}

__device__ __forceinline__ void red_add(float* p, float v) {
    asm volatile("red.global.add.f32 [%0], %1;" :: "l"(p), "f"(v) : "memory");
}

#define CP_ASYNC16(dst_u32, src_ptr) \
    asm volatile("cp.async.cg.shared.global [%0], [%1], 16;" \
        :: "r"(dst_u32), "l"(src_ptr) : "memory")
#define CP_COMMIT() asm volatile("cp.async.commit_group;" ::: "memory")
#define CP_WAIT0()  asm volatile("cp.async.wait_group 0;" ::: "memory")

// Quarter-domain named barrier: quarters 0..3 use HW barriers 1..4, 128 threads each.
#define BAR_QUART(qd) \
    asm volatile("bar.sync %0, 128;" :: "r"(1 + (qd)) : "memory")

// ===================== kernel 1: L2-normalize rows + zero accumulators =====================
__global__ __launch_bounds__(256) void norm_kernel(const float* __restrict__ in) {
    size_t gid = (size_t)blockIdx.x * 256 + threadIdx.x;
    if (gid < N_ROWS) g_sum[gid] = 0.0f;
    if (gid == 0) g_done = 0;

    int wid = threadIdx.x >> 5;
    int lane = threadIdx.x & 31;
    int row = blockIdx.x * 8 + wid;

    const float4* p = reinterpret_cast<const float4*>(in + (size_t)row * DIMK) + lane * 2;
    float4 a = p[0];
    float4 b = p[1];
    float ss = a.x * a.x + a.y * a.y + a.z * a.z + a.w * a.w
             + b.x * b.x + b.y * b.y + b.z * b.z + b.w * b.w;
#pragma unroll
    for (int o = 16; o > 0; o >>= 1) ss += __shfl_xor_sync(0xffffffffu, ss, o);

    float nrm = fmaxf(sqrtf(ss), 1e-12f);
    float sc = 1.0f / nrm;

    __nv_bfloat162 h0 = __floats2bfloat162_rn(a.x * sc, a.y * sc);
    __nv_bfloat162 h1 = __floats2bfloat162_rn(a.z * sc, a.w * sc);
    __nv_bfloat162 h2 = __floats2bfloat162_rn(b.x * sc, b.y * sc);
    __nv_bfloat162 h3 = __floats2bfloat162_rn(b.z * sc, b.w * sc);
    uint4 u;
    u.x = *reinterpret_cast<uint32_t*>(&h0);
    u.y = *reinterpret_cast<uint32_t*>(&h1);
    u.z = *reinterpret_cast<uint32_t*>(&h2);
    u.w = *reinterpret_cast<uint32_t*>(&h3);
    g_emb4[(size_t)row * 32 + lane] = u;
}

// ===================== kernel 2: triangular GEMM + symmetric LSE + final reduce =====================
// SMEM: A @0 (64KB, shared by all quarters),
//       8 B slabs of 16KB: quarter qd pair-slabs {SLAB(qd,0), SLAB(qd,1)},
//       s_red[16] tail
#define SM_A     0
#define SM_B     65536
#define SLAB(qd, b) (SM_B + (((qd) * 2 + (b)) << 14))
#define SM_TAIL  196608
#define DYN_SMEM (196608 + 128)

// A tile: 128 rows x 512B, per-row 16B-chunk XOR swizzle. All 512 threads.
__device__ __forceinline__ void load_A_async(uint32_t dst_u, int row0, int tid) {
#pragma unroll
    for (int it = 0; it < 8; ++it) {
        int c = tid + it * NTHR;          // 0..4095
        int i = c >> 5;                   // row 0..127
        int j = c & 31;
        uint32_t off = ((uint32_t)i << 9) + ((uint32_t)(j ^ (i & 7)) << 4);
        CP_ASYNC16(dst_u + off, &g_emb4[(size_t)(row0 + i) * 32 + j]);
    }
}

// B quarter-slab: 32 rows (J*128 + qd*32 ...) x 512B, loaded by the quarter's 128 threads.
__device__ __forceinline__ void load_B_async(uint32_t dst_u, int J, int qd, int lt) {
#pragma unroll
    for (int it = 0; it < 8; ++it) {
        int c = lt + it * 128;            // 0..1023
        int i = c >> 5;                   // row 0..31
        int j = c & 31;
        uint32_t off = ((uint32_t)i << 9) + ((uint32_t)(j ^ (i & 7)) << 4);
        CP_ASYNC16(dst_u + off, &g_emb4[(size_t)(J * TILE + qd * 32 + i) * 32 + j]);
    }
}

// Column flush: shfl-reduce over the 8 g-lanes, lanes 0-3 RED their 8 cols.
__device__ __forceinline__ void col_flush(
    float (&colacc)[8], bool skip, int base_col, int lane)
{
#pragma unroll
    for (int j = 0; j < 8; j++) {
        float v = colacc[j];
        v += __shfl_xor_sync(0xffffffffu, v, 4);
        v += __shfl_xor_sync(0xffffffffu, v, 8);
        v += __shfl_xor_sync(0xffffffffu, v, 16);
        if (lane < 4 && !skip) {
            int cc = (j >> 1) * 8 + lane * 2 + (j & 1);
            red_add(&g_sum[base_col + cc], v);
        }
        colacc[j] = 0.0f;
    }
}

// Epilogue + column flush for one 32x32 warp-slice of tile J.
__device__ __forceinline__ void epi_tile(
    const float (&acc)[2][4][4], float (&rowacc)[4], float (&colacc)[8],
    int I, int J, int qd, int warp_m, int g, int tg, int lane)
{
    bool diag_tile = (J == I);
#pragma unroll
    for (int mf = 0; mf < 2; mf++)
#pragma unroll
        for (int nf = 0; nf < 4; nf++)
#pragma unroll
            for (int e = 0; e < 4; e++) {
                float s = acc[mf][nf][e];
                float ex = ex2f(fmaf(s, C1F, -C1F));   // exp((s-1)/T)
                rowacc[mf * 2 + (e >> 1)] += ex;
                colacc[nf * 2 + (e & 1)] += ex;
                if (diag_tile) {
                    int rr = warp_m * 32 + mf * 16 + g + ((e >> 1) << 3);
                    int cloc = qd * 32 + nf * 8 + (tg << 1) + (e & 1);
                    if (rr == cloc) g_diag[I * TILE + rr] = s;
                }
            }
    col_flush(colacc, diag_tile, J * TILE + qd * 32, lane);
}

// MMA over one pair (or single) of J tiles with A-fragment reuse per K-step.
// Warp tile: 32 rows x 32 cols; B slab holds 32 rows (cols of S).
template <bool DUAL>
__device__ __forceinline__ void mma_pair(
    uint32_t b_u0, uint32_t b_u1,
    float (&acc0)[2][4][4], float (&acc1)[2][4][4],
    const uint32_t (&a_base)[2], const uint32_t (&a_rx)[2], uint32_t a_hi,
    const uint32_t (&b_roff)[2], uint32_t b_rx, uint32_t b_kb)
{
#pragma unroll
    for (int ks = 0; ks < 16; ks++) {
        uint32_t a[2][4];
#pragma unroll
        for (int mf = 0; mf < 2; mf++) {
            uint32_t ch = ((uint32_t)(ks * 2) + a_hi) ^ a_rx[mf];
            ldsm4(a[mf], a_base[mf] + (ch << 4));
        }
        uint32_t chb = (((uint32_t)(ks * 2) + b_kb) ^ b_rx) << 4;

        uint32_t b0[2][4];
#pragma unroll
        for (int np = 0; np < 2; np++)
            ldsm4(b0[np], b_u0 + b_roff[np] + chb);
#pragma unroll
        for (int mf = 0; mf < 2; mf++)
#pragma unroll
            for (int np = 0; np < 2; np++) {
                if (ks == 0) {
                    mma16816_z(acc0[mf][np * 2 + 0], a[mf], b0[np][0], b0[np][1]);
                    mma16816_z(acc0[mf][np * 2 + 1], a[mf], b0[np][2], b0[np][3]);
                } else {
                    mma16816(acc0[mf][np * 2 + 0], a[mf], b0[np][0], b0[np][1]);
                    mma16816(acc0[mf][np * 2 + 1], a[mf], b0[np][2], b0[np][3]);
                }
            }
        if (DUAL) {
            uint32_t b1[2][4];
#pragma unroll
            for (int np = 0; np < 2; np++)
                ldsm4(b1[np], b_u1 + b_roff[np] + chb);
#pragma unroll
            for (int mf = 0; mf < 2; mf++)
#pragma unroll
                for (int np = 0; np < 2; np++) {
                    if (ks == 0) {
                        mma16816_z(acc1[mf][np * 2 + 0], a[mf], b1[np][0], b1[np][1]);
                        mma16816_z(acc1[mf][np * 2 + 1], a[mf], b1[np][2], b1[np][3]);
                    } else {
                        mma16816(acc1[mf][np * 2 + 0], a[mf], b1[np][0], b1[np][1]);
                        mma16816(acc1[mf][np * 2 + 1], a[mf], b1[np][2], b1[np][3]);
                    }
                }
        }
    }
}

__global__ __launch_bounds__(NTHR, 1) void gemm_lse_kernel(float* __restrict__ out) {
    extern __shared__ char smem[];
    uint32_t su = smem_to_u32(smem);
    float* s_red = reinterpret_cast<float*>(smem + SM_TAIL);
    __shared__ unsigned int s_ticket;

    int tid = threadIdx.x;
    int lane = tid & 31;
    int wid = tid >> 5;
    int qd = wid >> 2;         // quarter-domain 0..3 (one warp per SMSP each)
    int warp_m = wid & 3;      // 0..3 (32 rows each); also the warp's SMSP
    int lt = tid & 127;        // thread in quarter
    const int g = lane >> 2;
    const int tg = lane & 3;
    const int cta = (int)blockIdx.x;

    // ldmatrix addressing (A buffer fixed at SM_A)
    uint32_t a_base[2];
    uint32_t a_rx[2];
#pragma unroll
    for (int mf = 0; mf < 2; mf++) {
        int r = warp_m * 32 + mf * 16 + (lane & 15);
        a_base[mf] = su + SM_A + ((uint32_t)r << 9);
        a_rx[mf] = (uint32_t)(r & 7);
    }
    uint32_t a_hi = (uint32_t)(lane >> 4);

    int nB = (lane & 7) + ((lane >> 4) << 3);
    uint32_t b_roff[2];
#pragma unroll
    for (int np = 0; np < 2; np++)
        b_roff[np] = (uint32_t)((np * 16 + nB) << 9);   // row 0..31 in 16KB slab
    uint32_t b_rx = (uint32_t)(lane & 7);
    uint32_t b_kb = (uint32_t)((lane >> 3) & 1);

    float colacc[8];
#pragma unroll
    for (int j = 0; j < 8; j++) colacc[j] = 0.0f;

    // Balanced triangular chunking: 8256 tiles of 128x128 in pair order;
    // CTA gets 55/56 contiguous tiles.
    int t_beg = cta * 55 + (cta < 116 ? cta : 116);
    int t_end = t_beg + 55 + (cta < 116 ? 1 : 0);

    int t = t_beg;
    while (t < t_end) {
        int q = t / 129;
        int r = t - q * 129;
        int I, J0, rowrem;
        if (r < 128 - q) { I = q; J0 = q + r; rowrem = 128 - q - r; }
        else { int r2 = r - (128 - q); I = 127 - q; J0 = 127 - q + r2; rowrem = q + 1 - r2; }
        int cnt = min(t_end - t, rowrem);

        // ---------------- sweep: A = block I (shared); each quarter does the
        //                  qd*32 column slice of B blocks J0..J0+cnt-1, in pairs ----
        float rowacc[4];
#pragma unroll
        for (int j = 0; j < 4; j++) rowacc[j] = 0.0f;

        load_A_async(su + SM_A, I * TILE, tid);
        load_B_async(su + SLAB(qd, 0), J0, qd, lt);
        if (cnt > 1)
            load_B_async(su + SLAB(qd, 1), J0 + 1, qd, lt);
        CP_COMMIT();
        CP_WAIT0();
        __syncthreads();   // publish A + all quarters' first pair

        uint32_t b_u0 = su + SLAB(qd, 0);
        uint32_t b_u1 = su + SLAB(qd, 1);

        int i = 0;
        while (i < cnt) {
            bool dual = (i + 1 < cnt);
            float acc0[2][4][4], acc1[2][4][4];

            if (dual)
                mma_pair<true>(b_u0, b_u1, acc0, acc1,
                               a_base, a_rx, a_hi, b_roff, b_rx, b_kb);
            else
                mma_pair<false>(b_u0, b_u1, acc0, acc1,
                                a_base, a_rx, a_hi, b_roff, b_rx, b_kb);

            BAR_QUART(qd);   // this quarter done reading its pair slabs

            // issue next pair's loads into the freed slabs (overlap with epi)
            int nxt = i + 2;
            int nload = cnt - nxt;
            if (nload > 0) {
                load_B_async(su + SLAB(qd, 0), J0 + nxt, qd, lt);
                if (nload > 1)
                    load_B_async(su + SLAB(qd, 1), J0 + nxt + 1, qd, lt);
                CP_COMMIT();
            }

            // epilogues (register-only + RED) overlap other quarters' MMA
            epi_tile(acc0, rowacc, colacc, I, J0 + i, qd, warp_m, g, tg, lane);
            if (dual)
                epi_tile(acc1, rowacc, colacc, I, J0 + i + 1, qd, warp_m, g, tg, lane);

            if (nload > 0) {
                CP_WAIT0();
                BAR_QUART(qd);   // publish new pair to the quarter
            }
            i += 2;
        }

        // Row flush: all quarters RED their 32-col partials (atomics merge)
#pragma unroll
        for (int j = 0; j < 4; j++) {
            float v = rowacc[j];
            v += __shfl_xor_sync(0xffffffffu, v, 1);
            v += __shfl_xor_sync(0xffffffffu, v, 2);
            if (tg == 0) {
                int rr = warp_m * 32 + (j >> 1) * 16 + g + ((j & 1) << 3);
                red_add(&g_sum[I * TILE + rr], v);
            }
        }
        __syncthreads();   // all quarters done with A before next sweep reloads it

        t += cnt;
    }

    // ---------------- last-CTA final reduction ----------------
    __threadfence();
    __syncthreads();
    if (tid == 0) s_ticket = atomicAdd(&g_done, 1u);
    __syncthreads();
    if (s_ticket == (unsigned)(gridDim.x - 1)) {
        __threadfence();
        float part = 0.0f;
#pragma unroll 4
        for (int rr = tid; rr < N_ROWS; rr += NTHR) {
            float S = g_sum[rr];
            part += (1.0f - g_diag[rr]) * INV_T + __logf(S);
        }
#pragma unroll
        for (int o = 16; o > 0; o >>= 1) part += __shfl_xor_sync(0xffffffffu, part, o);
        if (lane == 0) s_red[wid] = part;
        __syncthreads();
        if (tid == 0) {
            float v = 0.0f;
#pragma unroll
            for (int w = 0; w < 16; w++) v += s_red[w];
            out[0] = v * (1.0f / (float)N_ROWS);
            g_done = 0;   // reset for next graph replay
        }
    }
}

// ===================== launch =====================
extern "C" void kernel_launch(void* const* d_in, const int* in_sizes, int n_in,
                              void* d_out, int out_size) {
    (void)in_sizes; (void)n_in; (void)out_size;
    const float* emb = (const float*)d_in[0];

    cudaFuncSetAttribute(gemm_lse_kernel,
                         cudaFuncAttributeMaxDynamicSharedMemorySize, DYN_SMEM);

    norm_kernel<<<N_ROWS / 8, 256>>>(emb);
    gemm_lse_kernel<<<NCTA, NTHR, DYN_SMEM>>>((float*)d_out);
}

// round 17
// speedup vs baseline: 1.1122x; 1.0120x over previous
#include <cuda_runtime.h>
#include <cuda_bf16.h>
#include <cstdint>

// ===================== problem constants =====================
#define N_ROWS 16384
#define DIMK   256
#define TILE   128
#define NCTA   148
#define NTHR   512

// exp((s-1)/T) = 2^(s*C1 - C1),  C1 = log2(e)/T,  T = 0.07
#define C1F   20.60992915555662f
#define INV_T 14.285714285714286f

// ===================== device globals (no allocs allowed) =====================
__device__ uint4 g_emb4[N_ROWS * DIMK / 8];   // normalized bf16 rows
__device__ float g_sum[N_ROWS];               // Σ_j exp((s_rj-1)/T) per row (atomic)
__device__ float g_diag[N_ROWS];
__device__ unsigned int g_done = 0;

// ===================== helpers =====================
__device__ __forceinline__ uint32_t smem_to_u32(const void* smem_ptr) {
    uint32_t addr;
    asm("{ .reg .u64 tmp; cvta.to.shared.u64 tmp, %1; cvt.u32.u64 %0, tmp; }"
        : "=r"(addr) : "l"(smem_ptr));
    return addr;
}

__device__ __forceinline__ void ldsm4(uint32_t* r, uint32_t addr) {
    asm volatile("ldmatrix.sync.aligned.m8n8.x4.shared.b16 {%0,%1,%2,%3}, [%4];"
        : "=r"(r[0]), "=r"(r[1]), "=r"(r[2]), "=r"(r[3]) : "r"(addr));
}

__device__ __forceinline__ void mma16816(float* c, const uint32_t* a, uint32_t b0, uint32_t b1) {
    asm volatile(
        "mma.sync.aligned.m16n8k16.row.col.f32.bf16.bf16.f32 "
        "{%0,%1,%2,%3}, {%4,%5,%6,%7}, {%8,%9}, {%0,%1,%2,%3};"
        : "+f"(c[0]), "+f"(c[1]), "+f"(c[2]), "+f"(c[3])
        : "r"(a[0]), "r"(a[1]), "r"(a[2]), "r"(a[3]), "r"(b0), "r"(b1));
}

__device__ __forceinline__ void mma16816_z(float* c, const uint32_t* a, uint32_t b0, uint32_t b1) {
    asm volatile(
        "mma.sync.aligned.m16n8k16.row.col.f32.bf16.bf16.f32 "
        "{%0,%1,%2,%3}, {%4,%5,%6,%7}, {%8,%9}, {%10,%10,%10,%10};"
        : "=f"(c[0]), "=f"(c[1]), "=f"(c[2]), "=f"(c[3])
        : "r"(a[0]), "r"(a[1]), "r"(a[2]), "r"(a[3]), "r"(b0), "r"(b1), "f"(0.0f));
}

__device__ __forceinline__ float ex2f(float x) {
    float r;
    asm("ex2.approx.f32 %0, %1;" : "=f"(r) : "f"(x));
    return r;
}

__device__ __forceinline__ void red_add(float* p, float v) {
    asm volatile("red.global.add.f32 [%0], %1;" :: "l"(p), "f"(v) : "memory");
}

#define CP_ASYNC16(dst_u32, src_ptr) \
    asm volatile("cp.async.cg.shared.global [%0], [%1], 16;" \
        :: "r"(dst_u32), "l"(src_ptr) : "memory")
#define CP_COMMIT() asm volatile("cp.async.commit_group;" ::: "memory")
#define CP_WAIT0()  asm volatile("cp.async.wait_group 0;" ::: "memory")

// Quarter-domain named barrier: quarters 0..3 use HW barriers 1..4, 128 threads each.
#define BAR_QUART(qd) \
    asm volatile("bar.sync %0, 128;" :: "r"(1 + (qd)) : "memory")

// ===================== kernel 1: L2-normalize rows + zero accumulators =====================
__global__ __launch_bounds__(256) void norm_kernel(const float* __restrict__ in) {
    size_t gid = (size_t)blockIdx.x * 256 + threadIdx.x;
    if (gid < N_ROWS) g_sum[gid] = 0.0f;
    if (gid == 0) g_done = 0;

    int wid = threadIdx.x >> 5;
    int lane = threadIdx.x & 31;
    int row = blockIdx.x * 8 + wid;

    const float4* p = reinterpret_cast<const float4*>(in + (size_t)row * DIMK) + lane * 2;
    float4 a = p[0];
    float4 b = p[1];
    float ss = a.x * a.x + a.y * a.y + a.z * a.z + a.w * a.w
             + b.x * b.x + b.y * b.y + b.z * b.z + b.w * b.w;
#pragma unroll
    for (int o = 16; o > 0; o >>= 1) ss += __shfl_xor_sync(0xffffffffu, ss, o);

    float nrm = fmaxf(sqrtf(ss), 1e-12f);
    float sc = 1.0f / nrm;

    __nv_bfloat162 h0 = __floats2bfloat162_rn(a.x * sc, a.y * sc);
    __nv_bfloat162 h1 = __floats2bfloat162_rn(a.z * sc, a.w * sc);
    __nv_bfloat162 h2 = __floats2bfloat162_rn(b.x * sc, b.y * sc);
    __nv_bfloat162 h3 = __floats2bfloat162_rn(b.z * sc, b.w * sc);
    uint4 u;
    u.x = *reinterpret_cast<uint32_t*>(&h0);
    u.y = *reinterpret_cast<uint32_t*>(&h1);
    u.z = *reinterpret_cast<uint32_t*>(&h2);
    u.w = *reinterpret_cast<uint32_t*>(&h3);
    g_emb4[(size_t)row * 32 + lane] = u;
}

// ===================== kernel 2: triangular GEMM + symmetric LSE + final reduce =====================
// SMEM: A @0 (64KB, shared by all quarters),
//       8 B slabs of 16KB: quarter qd slabs {SLAB(qd,0), SLAB(qd,1)}, tile m -> slab m&1,
//       s_red[16] tail
#define SM_A     0
#define SM_B     65536
#define SLAB(qd, b) (SM_B + (((qd) * 2 + (b)) << 14))
#define SM_TAIL  196608
#define DYN_SMEM (196608 + 128)

// A tile: 128 rows x 512B, per-row 16B-chunk XOR swizzle. All 512 threads.
__device__ __forceinline__ void load_A_async(uint32_t dst_u, int row0, int tid) {
#pragma unroll
    for (int it = 0; it < 8; ++it) {
        int c = tid + it * NTHR;          // 0..4095
        int i = c >> 5;                   // row 0..127
        int j = c & 31;
        uint32_t off = ((uint32_t)i << 9) + ((uint32_t)(j ^ (i & 7)) << 4);
        CP_ASYNC16(dst_u + off, &g_emb4[(size_t)(row0 + i) * 32 + j]);
    }
}

// B quarter-slab: 32 rows (J*128 + qd*32 ...) x 512B, loaded by the quarter's 128 threads.
__device__ __forceinline__ void load_B_async(uint32_t dst_u, int J, int qd, int lt) {
#pragma unroll
    for (int it = 0; it < 8; ++it) {
        int c = lt + it * 128;            // 0..1023
        int i = c >> 5;                   // row 0..31
        int j = c & 31;
        uint32_t off = ((uint32_t)i << 9) + ((uint32_t)(j ^ (i & 7)) << 4);
        CP_ASYNC16(dst_u + off, &g_emb4[(size_t)(J * TILE + qd * 32 + i) * 32 + j]);
    }
}

// Column flush: shfl-reduce over the 8 g-lanes, lanes 0-3 RED their 8 cols.
__device__ __forceinline__ void col_flush(
    float (&colacc)[8], bool skip, int base_col, int lane)
{
#pragma unroll
    for (int j = 0; j < 8; j++) {
        float v = colacc[j];
        v += __shfl_xor_sync(0xffffffffu, v, 4);
        v += __shfl_xor_sync(0xffffffffu, v, 8);
        v += __shfl_xor_sync(0xffffffffu, v, 16);
        if (lane < 4 && !skip) {
            int cc = (j >> 1) * 8 + lane * 2 + (j & 1);
            red_add(&g_sum[base_col + cc], v);
        }
        colacc[j] = 0.0f;
    }
}

// Epilogue + column flush for one 32x32 warp-slice of tile J.
__device__ __forceinline__ void epi_tile(
    const float (&acc)[2][4][4], float (&rowacc)[4], float (&colacc)[8],
    int I, int J, int qd, int warp_m, int g, int tg, int lane)
{
    bool diag_tile = (J == I);
#pragma unroll
    for (int mf = 0; mf < 2; mf++)
#pragma unroll
        for (int nf = 0; nf < 4; nf++)
#pragma unroll
            for (int e = 0; e < 4; e++) {
                float s = acc[mf][nf][e];
                float ex = ex2f(fmaf(s, C1F, -C1F));   // exp((s-1)/T)
                rowacc[mf * 2 + (e >> 1)] += ex;
                colacc[nf * 2 + (e & 1)] += ex;
                if (diag_tile) {
                    int rr = warp_m * 32 + mf * 16 + g + ((e >> 1) << 3);
                    int cloc = qd * 32 + nf * 8 + (tg << 1) + (e & 1);
                    if (rr == cloc) g_diag[I * TILE + rr] = s;
                }
            }
    col_flush(colacc, diag_tile, J * TILE + qd * 32, lane);
}

// MMA over one group (1 or 2 J tiles) with A-fragment reuse per K-step.
// b_u0 = slab of first tile, b_u1 = slab of second tile (may be swapped order).
template <bool DUAL>
__device__ __forceinline__ void mma_pair(
    uint32_t b_u0, uint32_t b_u1,
    float (&acc0)[2][4][4], float (&acc1)[2][4][4],
    const uint32_t (&a_base)[2], const uint32_t (&a_rx)[2], uint32_t a_hi,
    const uint32_t (&b_roff)[2], uint32_t b_rx, uint32_t b_kb)
{
#pragma unroll
    for (int ks = 0; ks < 16; ks++) {
        uint32_t a[2][4];
#pragma unroll
        for (int mf = 0; mf < 2; mf++) {
            uint32_t ch = ((uint32_t)(ks * 2) + a_hi) ^ a_rx[mf];
            ldsm4(a[mf], a_base[mf] + (ch << 4));
        }
        uint32_t chb = (((uint32_t)(ks * 2) + b_kb) ^ b_rx) << 4;

        uint32_t b0[2][4];
#pragma unroll
        for (int np = 0; np < 2; np++)
            ldsm4(b0[np], b_u0 + b_roff[np] + chb);
#pragma unroll
        for (int mf = 0; mf < 2; mf++)
#pragma unroll
            for (int np = 0; np < 2; np++) {
                if (ks == 0) {
                    mma16816_z(acc0[mf][np * 2 + 0], a[mf], b0[np][0], b0[np][1]);
                    mma16816_z(acc0[mf][np * 2 + 1], a[mf], b0[np][2], b0[np][3]);
                } else {
                    mma16816(acc0[mf][np * 2 + 0], a[mf], b0[np][0], b0[np][1]);
                    mma16816(acc0[mf][np * 2 + 1], a[mf], b0[np][2], b0[np][3]);
                }
            }
        if (DUAL) {
            uint32_t b1[2][4];
#pragma unroll
            for (int np = 0; np < 2; np++)
                ldsm4(b1[np], b_u1 + b_roff[np] + chb);
#pragma unroll
            for (int mf = 0; mf < 2; mf++)
#pragma unroll
                for (int np = 0; np < 2; np++) {
                    if (ks == 0) {
                        mma16816_z(acc1[mf][np * 2 + 0], a[mf], b1[np][0], b1[np][1]);
                        mma16816_z(acc1[mf][np * 2 + 1], a[mf], b1[np][2], b1[np][3]);
                    } else {
                        mma16816(acc1[mf][np * 2 + 0], a[mf], b1[np][0], b1[np][1]);
                        mma16816(acc1[mf][np * 2 + 1], a[mf], b1[np][2], b1[np][3]);
                    }
                }
        }
    }
}

__global__ __launch_bounds__(NTHR, 1) void gemm_lse_kernel(float* __restrict__ out) {
    extern __shared__ char smem[];
    uint32_t su = smem_to_u32(smem);
    float* s_red = reinterpret_cast<float*>(smem + SM_TAIL);
    __shared__ unsigned int s_ticket;

    int tid = threadIdx.x;
    int lane = tid & 31;
    int wid = tid >> 5;
    int qd = wid >> 2;         // quarter-domain 0..3 (one warp per SMSP each)
    int warp_m = wid & 3;      // 0..3 (32 rows each); also the warp's SMSP
    int lt = tid & 127;        // thread in quarter
    const int g = lane >> 2;
    const int tg = lane & 3;
    const int cta = (int)blockIdx.x;

    // ldmatrix addressing (A buffer fixed at SM_A)
    uint32_t a_base[2];
    uint32_t a_rx[2];
#pragma unroll
    for (int mf = 0; mf < 2; mf++) {
        int r = warp_m * 32 + mf * 16 + (lane & 15);
        a_base[mf] = su + SM_A + ((uint32_t)r << 9);
        a_rx[mf] = (uint32_t)(r & 7);
    }
    uint32_t a_hi = (uint32_t)(lane >> 4);

    int nB = (lane & 7) + ((lane >> 4) << 3);
    uint32_t b_roff[2];
#pragma unroll
    for (int np = 0; np < 2; np++)
        b_roff[np] = (uint32_t)((np * 16 + nB) << 9);   // row 0..31 in 16KB slab
    uint32_t b_rx = (uint32_t)(lane & 7);
    uint32_t b_kb = (uint32_t)((lane >> 3) & 1);

    float colacc[8];
#pragma unroll
    for (int j = 0; j < 8; j++) colacc[j] = 0.0f;

    // Balanced triangular chunking: 8256 tiles of 128x128 in pair order;
    // CTA gets 55/56 contiguous tiles.
    int t_beg = cta * 55 + (cta < 116 ? cta : 116);
    int t_end = t_beg + 55 + (cta < 116 ? 1 : 0);

    int t = t_beg;
    while (t < t_end) {
        int q = t / 129;
        int r = t - q * 129;
        int I, J0, rowrem;
        if (r < 128 - q) { I = q; J0 = q + r; rowrem = 128 - q - r; }
        else { int r2 = r - (128 - q); I = 127 - q; J0 = 127 - q + r2; rowrem = q + 1 - r2; }
        int cnt = min(t_end - t, rowrem);

        // ---------------- sweep: A = block I (shared); each quarter does the
        //   qd*32 column slice of B blocks J0..J0+cnt-1 in groups.
        //   Odd quarters take a 1-tile first group -> permanent half-pair phase
        //   stagger vs even quarters. Tile m lives in slab m&1. ----------
        float rowacc[4];
#pragma unroll
        for (int j = 0; j < 4; j++) rowacc[j] = 0.0f;

        load_A_async(su + SM_A, I * TILE, tid);
        load_B_async(su + SLAB(qd, 0), J0, qd, lt);
        if (cnt > 1)
            load_B_async(su + SLAB(qd, 1), J0 + 1, qd, lt);
        CP_COMMIT();
        CP_WAIT0();
        __syncthreads();   // publish A + all quarters' first tiles

        int L = (cnt > 1) ? 2 : 1;   // tiles loaded (exclusive)
        int m0 = 0;
        bool first = true;
        while (m0 < cnt) {
            int take = ((qd & 1) && first) ? 1 : min(2, cnt - m0);
            first = false;
            bool dual = (take == 2);

            uint32_t bu_a = su + SLAB(qd, m0 & 1);
            uint32_t bu_b = su + SLAB(qd, (m0 + 1) & 1);
            float acc0[2][4][4], acc1[2][4][4];

            if (dual)
                mma_pair<true>(bu_a, bu_b, acc0, acc1,
                               a_base, a_rx, a_hi, b_roff, b_rx, b_kb);
            else
                mma_pair<false>(bu_a, bu_b, acc0, acc1,
                                a_base, a_rx, a_hi, b_roff, b_rx, b_kb);

            BAR_QUART(qd);   // this quarter done reading slabs of this group

            bool more = (m0 + take < cnt);
            if (more) {
                // load next tiles into the just-freed slabs (overlap with epi)
                int nload = cnt - L;
                if (nload > take) nload = take;
                if (nload > 0) {
                    load_B_async(su + SLAB(qd, L & 1), J0 + L, qd, lt);
                    if (nload > 1)
                        load_B_async(su + SLAB(qd, (L + 1) & 1), J0 + L + 1, qd, lt);
                    CP_COMMIT();
                    L += nload;
                }
            }

            // epilogues (register-only + RED) overlap other quarters' MMA
            epi_tile(acc0, rowacc, colacc, I, J0 + m0, qd, warp_m, g, tg, lane);
            if (dual)
                epi_tile(acc1, rowacc, colacc, I, J0 + m0 + 1, qd, warp_m, g, tg, lane);

            if (more) {
                CP_WAIT0();
                BAR_QUART(qd);   // publish next group's tiles to the quarter
            }
            m0 += take;
        }

        // Row flush: all quarters RED their 32-col partials (atomics merge)
#pragma unroll
        for (int j = 0; j < 4; j++) {
            float v = rowacc[j];
            v += __shfl_xor_sync(0xffffffffu, v, 1);
            v += __shfl_xor_sync(0xffffffffu, v, 2);
            if (tg == 0) {
                int rr = warp_m * 32 + (j >> 1) * 16 + g + ((j & 1) << 3);
                red_add(&g_sum[I * TILE + rr], v);
            }
        }
        __syncthreads();   // all quarters done with A before next sweep reloads it

        t += cnt;
    }

    // ---------------- last-CTA final reduction ----------------
    __threadfence();
    __syncthreads();
    if (tid == 0) s_ticket = atomicAdd(&g_done, 1u);
    __syncthreads();
    if (s_ticket == (unsigned)(gridDim.x - 1)) {
        __threadfence();
        float part = 0.0f;
#pragma unroll 4
        for (int rr = tid; rr < N_ROWS; rr += NTHR) {
            float S = g_sum[rr];
            part += (1.0f - g_diag[rr]) * INV_T + __logf(S);
        }
#pragma unroll
        for (int o = 16; o > 0; o >>= 1) part += __shfl_xor_sync(0xffffffffu, part, o);
        if (lane == 0) s_red[wid] = part;
        __syncthreads();
        if (tid == 0) {
            float v = 0.0f;
#pragma unroll
            for (int w = 0; w < 16; w++) v += s_red[w];
            out[0] = v * (1.0f / (float)N_ROWS);
            g_done = 0;   // reset for next graph replay
        }
    }
}

// ===================== launch =====================
extern "C" void kernel_launch(void* const* d_in, const int* in_sizes, int n_in,
                              void* d_out, int out_size) {
    (void)in_sizes; (void)n_in; (void)out_size;
    const float* emb = (const float*)d_in[0];

    cudaFuncSetAttribute(gemm_lse_kernel,
                         cudaFuncAttributeMaxDynamicSharedMemorySize, DYN_SMEM);

    norm_kernel<<<N_ROWS / 8, 256>>>(emb);
    gemm_lse_kernel<<<NCTA, NTHR, DYN_SMEM>>>((float*)d_out);
}